// round 1
// baseline (speedup 1.0000x reference)
#include <cuda_runtime.h>
#include <math.h>

// Problem constants
#define BB   2
#define SS   2048
#define DD   2048
#define HH   16
#define HD   128
#define DFF  8192
#define MROW (BB*SS)   // 4096
#define EPSV 1e-5f

// ---------------- scratch (device globals; allocation-free) ----------------
static __device__ float g_xn [(size_t)MROW*DD];
static __device__ float g_q  [(size_t)MROW*DD];
static __device__ float g_k  [(size_t)MROW*DD];
static __device__ float g_v  [(size_t)MROW*DD];
static __device__ float g_ctx[(size_t)MROW*DD];
static __device__ float g_h  [(size_t)MROW*DD];
static __device__ float g_ff [(size_t)MROW*DFF];

// ---------------- LayerNorm ----------------
__global__ __launch_bounds__(256)
void ln_kernel(const float* __restrict__ x, const float* __restrict__ sc,
               const float* __restrict__ sh, float* __restrict__ out) {
    int row = blockIdx.x;
    const float* xr = x + (size_t)row * DD;
    float v[8];
    float s = 0.f, sq = 0.f;
#pragma unroll
    for (int i = 0; i < 8; i++) {
        v[i] = xr[threadIdx.x + i*256];
        s  += v[i];
        sq += v[i]*v[i];
    }
    __shared__ float rs[8], rq[8];
    __shared__ float s_mean, s_rstd;
#pragma unroll
    for (int o = 16; o > 0; o >>= 1) {
        s  += __shfl_down_sync(0xFFFFFFFFu, s,  o);
        sq += __shfl_down_sync(0xFFFFFFFFu, sq, o);
    }
    int w = threadIdx.x >> 5;
    if ((threadIdx.x & 31) == 0) { rs[w] = s; rq[w] = sq; }
    __syncthreads();
    if (threadIdx.x == 0) {
        float ts = 0.f, tq = 0.f;
#pragma unroll
        for (int i = 0; i < 8; i++) { ts += rs[i]; tq += rq[i]; }
        float mean = ts * (1.0f/DD);
        float var  = tq * (1.0f/DD) - mean*mean;
        s_mean = mean;
        s_rstd = rsqrtf(var + EPSV);
    }
    __syncthreads();
    float mean = s_mean, rstd = s_rstd;
    float* orow = out + (size_t)row * DD;
#pragma unroll
    for (int i = 0; i < 8; i++) {
        int d = threadIdx.x + i*256;
        orow[d] = sc[d] * (v[i] - mean) * rstd + sh[d];
    }
}

// ---------------- GELU ----------------
__device__ __forceinline__ float gelu_f(float x) {
    float x3 = x*x*x;
    return 0.5f * x * (1.0f + tanhf(0.79788456080286536f * (x + 0.044715f*x3)));
}

// ---------------- GEMM: C[M,N] = A[M,K] @ B[K,N] (+epilogue) ----------------
// EPI 0: plain   EPI 1: +bias[n] + R[m,n]   EPI 2: gelu(+bias[n])
template<int EPI>
__global__ __launch_bounds__(256)
void gemm_kernel(const float* __restrict__ A, const float* __restrict__ Bm,
                 const float* __restrict__ bias, const float* __restrict__ R,
                 float* __restrict__ C, int N, int K) {
    __shared__ float As[16][132];
    __shared__ float Bs[16][128];
    int tid = threadIdx.x;
    int tx = tid & 15, ty = tid >> 4;
    int m0 = blockIdx.y * 128, n0 = blockIdx.x * 128;

    float acc[8][8];
#pragma unroll
    for (int i = 0; i < 8; i++)
#pragma unroll
        for (int j = 0; j < 8; j++) acc[i][j] = 0.f;

    int arow = tid >> 2;          // 0..63
    int akg  = (tid & 3) * 4;     // 0,4,8,12
    int brow = tid >> 5;          // 0..7
    int bcol = (tid & 31) * 4;    // 0..124

    const float* Aptr = A + (size_t)(m0 + arow) * K + akg;
    const float* Bptr = Bm + (size_t)brow * N + n0 + bcol;

    for (int kt = 0; kt < K; kt += 16) {
        float4 a0 = *(const float4*)(Aptr);
        float4 a1 = *(const float4*)(Aptr + (size_t)64 * K);
        float4 b0 = *(const float4*)(Bptr);
        float4 b1 = *(const float4*)(Bptr + (size_t)8 * N);
        As[akg+0][arow] = a0.x; As[akg+1][arow] = a0.y;
        As[akg+2][arow] = a0.z; As[akg+3][arow] = a0.w;
        As[akg+0][arow+64] = a1.x; As[akg+1][arow+64] = a1.y;
        As[akg+2][arow+64] = a1.z; As[akg+3][arow+64] = a1.w;
        *(float4*)&Bs[brow  ][bcol] = b0;
        *(float4*)&Bs[brow+8][bcol] = b1;
        __syncthreads();
#pragma unroll
        for (int k = 0; k < 16; k++) {
            float a[8], b[8];
            *(float4*)(a)   = *(float4*)&As[k][ty*8];
            *(float4*)(a+4) = *(float4*)&As[k][ty*8+4];
            *(float4*)(b)   = *(float4*)&Bs[k][tx*8];
            *(float4*)(b+4) = *(float4*)&Bs[k][tx*8+4];
#pragma unroll
            for (int i = 0; i < 8; i++)
#pragma unroll
                for (int j = 0; j < 8; j++)
                    acc[i][j] += a[i]*b[j];
        }
        __syncthreads();
        Aptr += 16;
        Bptr += (size_t)16 * N;
    }

#pragma unroll
    for (int i = 0; i < 8; i++) {
        int m = m0 + ty*8 + i;
#pragma unroll
        for (int j = 0; j < 8; j += 4) {
            int n = n0 + tx*8 + j;
            float4 o;
            float vv[4];
#pragma unroll
            for (int u = 0; u < 4; u++) vv[u] = acc[i][j+u];
            if (EPI == 1) {
                float4 bb = *(const float4*)(bias + n);
                float4 rr = *(const float4*)(R + (size_t)m * N + n);
                vv[0] += bb.x + rr.x; vv[1] += bb.y + rr.y;
                vv[2] += bb.z + rr.z; vv[3] += bb.w + rr.w;
            } else if (EPI == 2) {
                float4 bb = *(const float4*)(bias + n);
                vv[0] = gelu_f(vv[0] + bb.x); vv[1] = gelu_f(vv[1] + bb.y);
                vv[2] = gelu_f(vv[2] + bb.z); vv[3] = gelu_f(vv[3] + bb.w);
            }
            o.x = vv[0]; o.y = vv[1]; o.z = vv[2]; o.w = vv[3];
            *(float4*)(C + (size_t)m * N + n) = o;
        }
    }
}

// ---------------- Causal flash attention ----------------
// Q/K/V layout: [B,S,D] with head h occupying cols h*HD..h*HD+127.
// Block: 256 threads, 64 queries x (tiles of 64 keys). Dynamic smem.
#define ATT_SMEM_FLOATS (128*68 + 128*68 + 64*128 + 64*68 + 3*64)
#define ATT_SMEM_BYTES  (ATT_SMEM_FLOATS * 4)

__global__ __launch_bounds__(256)
void attn_kernel(const float* __restrict__ Q, const float* __restrict__ Kg,
                 const float* __restrict__ V, float* __restrict__ O) {
    extern __shared__ float sm[];
    float* Qt   = sm;                  // [128][68] transposed, pre-scaled
    float* Kt   = Qt + 128*68;         // [128][68] transposed
    float* Vs   = Kt + 128*68;         // [64][128]
    float* Ps   = Vs + 64*128;         // [64][68]
    float* mrow = Ps + 64*68;          // [64]
    float* lrow = mrow + 64;           // [64]
    float* frow = lrow + 64;           // [64]

    int tid = threadIdx.x;
    int tx = tid & 15, ty = tid >> 4;
    int q0 = blockIdx.x * 64;
    int b  = blockIdx.y >> 4;
    int h  = blockIdx.y & 15;
    const float rscale = 0.08838834764831845f;  // 1/sqrt(128)

    size_t base = ((size_t)b * SS) * DD + (size_t)h * HD;

    // load Q tile transposed + pre-scaled
#pragma unroll
    for (int i = 0; i < 8; i++) {
        int lin = tid + i*256;
        int r = lin >> 5;
        int d = (lin & 31) * 4;
        float4 qv = *(const float4*)(Q + base + (size_t)(q0 + r) * DD + d);
        Qt[(d+0)*68 + r] = qv.x * rscale;
        Qt[(d+1)*68 + r] = qv.y * rscale;
        Qt[(d+2)*68 + r] = qv.z * rscale;
        Qt[(d+3)*68 + r] = qv.w * rscale;
    }
    if (tid < 64) { mrow[tid] = -1e30f; lrow[tid] = 0.f; }

    float acc[4][8];
#pragma unroll
    for (int i = 0; i < 4; i++)
#pragma unroll
        for (int j = 0; j < 8; j++) acc[i][j] = 0.f;

    int ntiles = (q0 >> 6) + 1;
    for (int kt = 0; kt < ntiles; kt++) {
        int k0 = kt * 64;
        __syncthreads();   // previous tile fully consumed (also covers Qt on kt=0)
        // load K (transposed) and V (row-major) tiles
#pragma unroll
        for (int i = 0; i < 8; i++) {
            int lin = tid + i*256;
            int r = lin >> 5;
            int d = (lin & 31) * 4;
            float4 kv = *(const float4*)(Kg + base + (size_t)(k0 + r) * DD + d);
            Kt[(d+0)*68 + r] = kv.x;
            Kt[(d+1)*68 + r] = kv.y;
            Kt[(d+2)*68 + r] = kv.z;
            Kt[(d+3)*68 + r] = kv.w;
            float4 vv = *(const float4*)(V + base + (size_t)(k0 + r) * DD + d);
            *(float4*)&Vs[r*128 + d] = vv;
        }
        __syncthreads();

        // S = (Q*rscale) @ K^T for this tile: each thread 4x4
        float s[4][4];
#pragma unroll
        for (int i = 0; i < 4; i++)
#pragma unroll
            for (int j = 0; j < 4; j++) s[i][j] = 0.f;
#pragma unroll 8
        for (int d = 0; d < 128; d++) {
            float4 af = *(float4*)&Qt[d*68 + ty*4];
            float4 bf = *(float4*)&Kt[d*68 + tx*4];
            s[0][0] += af.x*bf.x; s[0][1] += af.x*bf.y; s[0][2] += af.x*bf.z; s[0][3] += af.x*bf.w;
            s[1][0] += af.y*bf.x; s[1][1] += af.y*bf.y; s[1][2] += af.y*bf.z; s[1][3] += af.y*bf.w;
            s[2][0] += af.z*bf.x; s[2][1] += af.z*bf.y; s[2][2] += af.z*bf.z; s[2][3] += af.z*bf.w;
            s[3][0] += af.w*bf.x; s[3][1] += af.w*bf.y; s[3][2] += af.w*bf.z; s[3][3] += af.w*bf.w;
        }
        bool diag = (kt == ntiles - 1);  // only the k0==q0 tile needs masking
#pragma unroll
        for (int i = 0; i < 4; i++) {
            int qi = ty*4 + i;
#pragma unroll
            for (int j = 0; j < 4; j++) {
                int kj = tx*4 + j;
                float val = s[i][j];
                if (diag && kj > qi) val = -1e30f;
                Ps[qi*68 + kj] = val;
            }
        }
        __syncthreads();

        // online softmax per row (64 rows on 64 threads)
        if (tid < 64) {
            int r = tid;
            float tm = -1e30f;
#pragma unroll 8
            for (int j = 0; j < 64; j++) tm = fmaxf(tm, Ps[r*68 + j]);
            float mo = mrow[r];
            float mn = fmaxf(mo, tm);
            float f  = __expf(mo - mn);
            float ps = 0.f;
#pragma unroll 8
            for (int j = 0; j < 64; j++) {
                float p = __expf(Ps[r*68 + j] - mn);
                Ps[r*68 + j] = p;
                ps += p;
            }
            lrow[r] = lrow[r]*f + ps;
            mrow[r] = mn;
            frow[r] = f;
        }
        __syncthreads();

        // rescale accumulators, then O += P @ V
        float fs[4];
#pragma unroll
        for (int i = 0; i < 4; i++) fs[i] = frow[ty*4 + i];
#pragma unroll
        for (int i = 0; i < 4; i++)
#pragma unroll
            for (int j = 0; j < 8; j++) acc[i][j] *= fs[i];
#pragma unroll 4
        for (int j = 0; j < 64; j++) {
            float p0 = Ps[(ty*4+0)*68 + j];
            float p1 = Ps[(ty*4+1)*68 + j];
            float p2 = Ps[(ty*4+2)*68 + j];
            float p3 = Ps[(ty*4+3)*68 + j];
            float4 v0 = *(float4*)&Vs[j*128 + tx*8];
            float4 v1 = *(float4*)&Vs[j*128 + tx*8 + 4];
            acc[0][0] += p0*v0.x; acc[0][1] += p0*v0.y; acc[0][2] += p0*v0.z; acc[0][3] += p0*v0.w;
            acc[0][4] += p0*v1.x; acc[0][5] += p0*v1.y; acc[0][6] += p0*v1.z; acc[0][7] += p0*v1.w;
            acc[1][0] += p1*v0.x; acc[1][1] += p1*v0.y; acc[1][2] += p1*v0.z; acc[1][3] += p1*v0.w;
            acc[1][4] += p1*v1.x; acc[1][5] += p1*v1.y; acc[1][6] += p1*v1.z; acc[1][7] += p1*v1.w;
            acc[2][0] += p2*v0.x; acc[2][1] += p2*v0.y; acc[2][2] += p2*v0.z; acc[2][3] += p2*v0.w;
            acc[2][4] += p2*v1.x; acc[2][5] += p2*v1.y; acc[2][6] += p2*v1.z; acc[2][7] += p2*v1.w;
            acc[3][0] += p3*v0.x; acc[3][1] += p3*v0.y; acc[3][2] += p3*v0.z; acc[3][3] += p3*v0.w;
            acc[3][4] += p3*v1.x; acc[3][5] += p3*v1.y; acc[3][6] += p3*v1.z; acc[3][7] += p3*v1.w;
        }
    }

    // write out ctx
#pragma unroll
    for (int i = 0; i < 4; i++) {
        int r = ty*4 + i;
        float inv = 1.0f / lrow[r];
        float4 o0, o1;
        o0.x = acc[i][0]*inv; o0.y = acc[i][1]*inv; o0.z = acc[i][2]*inv; o0.w = acc[i][3]*inv;
        o1.x = acc[i][4]*inv; o1.y = acc[i][5]*inv; o1.z = acc[i][6]*inv; o1.w = acc[i][7]*inv;
        float* op = O + base + (size_t)(q0 + r) * DD + tx*8;
        *(float4*)(op)     = o0;
        *(float4*)(op + 4) = o1;
    }
}

// ---------------- launch ----------------
extern "C" void kernel_launch(void* const* d_in, const int* in_sizes, int n_in,
                              void* d_out, int out_size) {
    const float* x    = (const float*)d_in[0];
    const float* Wq   = (const float*)d_in[1];
    const float* Wk   = (const float*)d_in[2];
    const float* Wv   = (const float*)d_in[3];
    const float* Wo   = (const float*)d_in[4];
    const float* bo   = (const float*)d_in[5];
    const float* ln1s = (const float*)d_in[6];
    const float* ln1b = (const float*)d_in[7];
    const float* ln2s = (const float*)d_in[8];
    const float* ln2b = (const float*)d_in[9];
    const float* W1   = (const float*)d_in[10];
    const float* b1   = (const float*)d_in[11];
    const float* W2   = (const float*)d_in[12];
    const float* b2   = (const float*)d_in[13];
    float* out = (float*)d_out;

    float *xn, *q, *k, *v, *ctx, *h, *ff;
    cudaGetSymbolAddress((void**)&xn,  g_xn);
    cudaGetSymbolAddress((void**)&q,   g_q);
    cudaGetSymbolAddress((void**)&k,   g_k);
    cudaGetSymbolAddress((void**)&v,   g_v);
    cudaGetSymbolAddress((void**)&ctx, g_ctx);
    cudaGetSymbolAddress((void**)&h,   g_h);
    cudaGetSymbolAddress((void**)&ff,  g_ff);

    cudaFuncSetAttribute(attn_kernel, cudaFuncAttributeMaxDynamicSharedMemorySize,
                         ATT_SMEM_BYTES);

    // 1) LN1
    ln_kernel<<<MROW, 256>>>(x, ln1s, ln1b, xn);
    // 2) QKV projections
    gemm_kernel<0><<<dim3(DD/128, MROW/128), 256>>>(xn, Wq, nullptr, nullptr, q, DD, DD);
    gemm_kernel<0><<<dim3(DD/128, MROW/128), 256>>>(xn, Wk, nullptr, nullptr, k, DD, DD);
    gemm_kernel<0><<<dim3(DD/128, MROW/128), 256>>>(xn, Wv, nullptr, nullptr, v, DD, DD);
    // 3) causal attention
    attn_kernel<<<dim3(SS/64, BB*HH), 256, ATT_SMEM_BYTES>>>(q, k, v, ctx);
    // 4) output projection + bias + residual
    gemm_kernel<1><<<dim3(DD/128, MROW/128), 256>>>(ctx, Wo, bo, x, h, DD, DD);
    // 5) LN2
    ln_kernel<<<MROW, 256>>>(h, ln2s, ln2b, xn);
    // 6) FFN up + GELU
    gemm_kernel<2><<<dim3(DFF/128, MROW/128), 256>>>(xn, W1, b1, nullptr, ff, DFF, DD);
    // 7) FFN down + bias + residual
    gemm_kernel<1><<<dim3(DD/128, MROW/128), 256>>>(ff, W2, b2, h, out, DD, DFF);
}